// round 13
// baseline (speedup 1.0000x reference)
#include <cuda_runtime.h>
#include <cuda_bf16.h>
#include <cstdint>

// B=8, SEQ=4096, DIM=64.
// out = scale * rope(Q) @ (rope(K)^T @ rope(V))   (associativity; no softmax)
// scale = 1/sqrt(64) = 0.125
// Tensor path: mma.sync.m16n8k8 TF32, 2-way split (3 MMAs) for fp32 accuracy.
// This round: occupancy-first shapes (128-thr CTAs, grid >= 1024).

#define BATCH  8
#define SEQ    4096
#define DIM    64
#define NC1    128         // k1 chunks per batch (32 rows each)
#define CH1    32
#define NGRP   8           // reduce tree fan-in groups (16 chunks each)

__device__ float g_partials[NC1 * BATCH * DIM * DIM];  // 16 MB
__device__ float g_p2[NGRP * BATCH * DIM * DIM];       // 1 MB
__device__ float g_M[BATCH * DIM * DIM];               // 128 KB

// ---------------------------------------------------------------------------
__device__ __forceinline__ uint32_t f2tf32(float x) {
    uint32_t r; asm("cvt.rna.tf32.f32 %0, %1;" : "=r"(r) : "f"(x)); return r;
}
__device__ __forceinline__ float4 rope4(float4 x, float4 f) {
    float4 o;
    o.x = x.x * f.x - x.y * f.y;  o.y = x.x * f.y + x.y * f.x;
    o.z = x.z * f.z - x.w * f.w;  o.w = x.z * f.w + x.w * f.z;
    return o;
}
__device__ __forceinline__ void mma8(float* c, const uint32_t* a, const uint32_t* b) {
    asm volatile(
        "mma.sync.aligned.m16n8k8.row.col.f32.tf32.tf32.f32 "
        "{%0,%1,%2,%3}, {%4,%5,%6,%7}, {%8,%9}, {%0,%1,%2,%3};\n"
        : "+f"(c[0]), "+f"(c[1]), "+f"(c[2]), "+f"(c[3])
        : "r"(a[0]), "r"(a[1]), "r"(a[2]), "r"(a[3]), "r"(b[0]), "r"(b[1]));
}
__device__ __forceinline__ void split1(float x, uint32_t& hi, uint32_t& lo) {
    hi = f2tf32(x);
    lo = __float_as_uint(x - __uint_as_float(hi));
}
__device__ __forceinline__ void split4(float4 v, float4& h, float4& l) {
    uint32_t h0, l0, h1, l1, h2, l2, h3, l3;
    split1(v.x, h0, l0); split1(v.y, h1, l1);
    split1(v.z, h2, l2); split1(v.w, h3, l3);
    h = make_float4(__uint_as_float(h0), __uint_as_float(h1),
                    __uint_as_float(h2), __uint_as_float(h3));
    l = make_float4(__uint_as_float(l0), __uint_as_float(l1),
                    __uint_as_float(l2), __uint_as_float(l3));
}

// ---------------------------------------------------------------------------
// Kernel 1: partial M = rope(K)^T @ rope(V) over a 32-row chunk.
// 1024 CTAs x 128 thr. 4 warps; warp w = m-tile (M rows 16w..16w+15),
// iterating all 32 seq rows (4 k-steps). Per-warp acc = 8 j-tiles x 4.
// K/V staged raw at stride 72 (fragment LDS = full bank permutation).
// ---------------------------------------------------------------------------
__global__ __launch_bounds__(128) void kv_outer_kernel(
    const float* __restrict__ K, const float* __restrict__ V,
    const float* __restrict__ FK, const float* __restrict__ FV)
{
    const int b = blockIdx.y;
    const int c = blockIdx.x;
    const int t = threadIdx.x;
    const int w = t >> 5;
    const int lane = t & 31;
    const int g = lane >> 2;
    const int tig = lane & 3;

    __shared__ float sk[CH1 * 72];   // 9.2 KB
    __shared__ float sv[CH1 * 72];   // 9.2 KB

    const float4* K4  = (const float4*)(K + (size_t)b * SEQ * DIM);
    const float4* V4  = (const float4*)(V + (size_t)b * SEQ * DIM);
    const float4* FK4 = (const float4*)FK;
    const float4* FV4 = (const float4*)FV;

    // stage 32 rows (512 float4 per tensor, 4 per thread), rope fused
#pragma unroll
    for (int u = 0; u < 4; u++) {
        const int f  = t + 128 * u;
        const int rr = f >> 4, cc = f & 15;
        const int gi = (c * CH1 + rr) * 16 + cc;
        *(float4*)&sk[rr * 72 + 4 * cc] = rope4(K4[gi], FK4[gi]);
        *(float4*)&sv[rr * 72 + 4 * cc] = rope4(V4[gi], FV4[gi]);
    }
    __syncthreads();

    const int m0 = 16 * w;

    float acc[8][4];
#pragma unroll
    for (int j = 0; j < 8; j++)
#pragma unroll
        for (int p = 0; p < 4; p++) acc[j][p] = 0.0f;

#pragma unroll
    for (int ks = 0; ks < 4; ks++) {
        const int krow = 8 * ks;
        uint32_t ah[4], al[4];
        {
            const float a0 = sk[(krow + tig)     * 72 + m0 + g];
            const float a1 = sk[(krow + tig)     * 72 + m0 + g + 8];
            const float a2 = sk[(krow + tig + 4) * 72 + m0 + g];
            const float a3 = sk[(krow + tig + 4) * 72 + m0 + g + 8];
            split1(a0, ah[0], al[0]); split1(a1, ah[1], al[1]);
            split1(a2, ah[2], al[2]); split1(a3, ah[3], al[3]);
        }
#pragma unroll
        for (int j = 0; j < 8; j++) {
            const int n0 = 8 * j;
            const float r0 = sv[(krow + tig)     * 72 + n0 + g];
            const float r1 = sv[(krow + tig + 4) * 72 + n0 + g];
            uint32_t bh[2], bl[2];
            split1(r0, bh[0], bl[0]);
            split1(r1, bh[1], bl[1]);
            mma8(acc[j], ah, bh);
            mma8(acc[j], ah, bl);
            mma8(acc[j], al, bh);
        }
    }

    // each warp writes its own 16 rows of the partial tile — no combine pass
    float* P = g_partials + ((size_t)c * BATCH + b) * (DIM * DIM);
#pragma unroll
    for (int j = 0; j < 8; j++) {
        const int col = 8 * j + 2 * tig;
        *(float2*)&P[(m0 + g)     * DIM + col] = make_float2(acc[j][0], acc[j][1]);
        *(float2*)&P[(m0 + g + 8) * DIM + col] = make_float2(acc[j][2], acc[j][3]);
    }
}

// ---------------------------------------------------------------------------
// Kernel 2a: tree reduce level 1. 65536 threads; thread (grp, o) sums
// chunks grp*16..grp*16+15 of float4 column o (16 MB read, BW-bound).
// ---------------------------------------------------------------------------
__global__ __launch_bounds__(256) void reduce_a_kernel()
{
    const int idx = blockIdx.x * 256 + threadIdx.x;   // 0..65535
    const int grp = idx >> 13;                        // 0..7
    const int o   = idx & 8191;                       // float4 column
    const float4* P = (const float4*)g_partials;
    float4 s0 = make_float4(0.f, 0.f, 0.f, 0.f);
    float4 s1 = make_float4(0.f, 0.f, 0.f, 0.f);
#pragma unroll
    for (int i = 0; i < 16; i += 2) {
        const float4 a = P[(size_t)(grp * 16 + i)     * 8192 + o];
        const float4 e = P[(size_t)(grp * 16 + i + 1) * 8192 + o];
        s0.x += a.x; s0.y += a.y; s0.z += a.z; s0.w += a.w;
        s1.x += e.x; s1.y += e.y; s1.z += e.z; s1.w += e.w;
    }
    ((float4*)g_p2)[(size_t)grp * 8192 + o] =
        make_float4(s0.x + s1.x, s0.y + s1.y, s0.z + s1.z, s0.w + s1.w);
}

// ---------------------------------------------------------------------------
// Kernel 2b: tree reduce level 2 (1 MB, L2-hot). 8192 threads.
// ---------------------------------------------------------------------------
__global__ __launch_bounds__(256) void reduce_b_kernel()
{
    const int o = blockIdx.x * 256 + threadIdx.x;     // 0..8191
    const float4* P = (const float4*)g_p2;
    float4 s0 = make_float4(0.f, 0.f, 0.f, 0.f);
    float4 s1 = make_float4(0.f, 0.f, 0.f, 0.f);
#pragma unroll
    for (int i = 0; i < NGRP; i += 2) {
        const float4 a = P[(size_t)i       * 8192 + o];
        const float4 e = P[(size_t)(i + 1) * 8192 + o];
        s0.x += a.x; s0.y += a.y; s0.z += a.z; s0.w += a.w;
        s1.x += e.x; s1.y += e.y; s1.z += e.z; s1.w += e.w;
    }
    ((float4*)g_M)[o] = make_float4(s0.x + s1.x, s0.y + s1.y,
                                    s0.z + s1.z, s0.w + s1.w);
}

// ---------------------------------------------------------------------------
// Kernel 3: out = scale * rope(Q) @ M[b].
// 2048 CTAs x 128 thr: CTA = 32 q-rows x 32-col slice of the output.
// M slice (64x32) pre-split hi/lo in smem at stride 40 (40%32=8 -> fragment
// LDS word = 8*tig+g+c: full bank permutation). q staged raw, stride 68.
// 4 warps: row-half (w&1) x col-sub (w>>1: 16 cols = 2 j-tiles).
// ---------------------------------------------------------------------------
__global__ __launch_bounds__(128) void qm_kernel(
    const float* __restrict__ Q, const float* __restrict__ FQ,
    float* __restrict__ OUT)
{
    const int b  = blockIdx.y;
    const int rc = blockIdx.x >> 1;       // 0..127: 32-row chunk
    const int chf = blockIdx.x & 1;       // col half: 0 or 1
    const int t  = threadIdx.x;
    const int w  = t >> 5;
    const int lane = t & 31;
    const int g = lane >> 2;
    const int tig = lane & 3;

    __shared__ float sMh[DIM * 40];   // 10.24 KB
    __shared__ float sMl[DIM * 40];   // 10.24 KB
    __shared__ float sq[CH1 * 68];    // 8.7 KB

    // ---- load + split M[b] slice: cols [32*chf, 32*chf+32), 512 float4 ----
    {
        const float4* M4 = (const float4*)(g_M + (size_t)b * DIM * DIM);
#pragma unroll
        for (int u = 0; u < 4; u++) {
            const int f  = t + 128 * u;    // 0..511
            const int k  = f >> 3;         // 0..63
            const int n4 = f & 7;          // float4 within the 32-col slice
            float4 h, l;
            split4(M4[k * 16 + 8 * chf + n4], h, l);
            *(float4*)&sMh[k * 40 + 4 * n4] = h;
            *(float4*)&sMl[k * 40 + 4 * n4] = l;
        }
    }

    // ---- stage 32 rope'd q rows ----
    const float4* Q4  = (const float4*)(Q + (size_t)b * SEQ * DIM);
    const float4* FQ4 = (const float4*)FQ;
#pragma unroll
    for (int u = 0; u < 4; u++) {
        const int f  = t + 128 * u;
        const int rr = f >> 4, cc = f & 15;
        const int gi = (rc * CH1 + rr) * 16 + cc;
        *(float4*)&sq[rr * 68 + 4 * cc] = rope4(Q4[gi], FQ4[gi]);
    }
    __syncthreads();

    const int m0s = 16 * (w & 1);         // row half within the 32 rows
    const int nsub = 16 * (w >> 1);       // col sub within the 32-col slice

    float cc2[2][4];
#pragma unroll
    for (int jj = 0; jj < 2; jj++)
#pragma unroll
        for (int p = 0; p < 4; p++) cc2[jj][p] = 0.0f;

#pragma unroll
    for (int ks = 0; ks < 8; ks++) {
        const int k0 = 8 * ks;
        uint32_t ah[4], al[4];
        {
            const float a0 = sq[(m0s + g)     * 68 + k0 + tig];
            const float a1 = sq[(m0s + g + 8) * 68 + k0 + tig];
            const float a2 = sq[(m0s + g)     * 68 + k0 + tig + 4];
            const float a3 = sq[(m0s + g + 8) * 68 + k0 + tig + 4];
            split1(a0, ah[0], al[0]); split1(a1, ah[1], al[1]);
            split1(a2, ah[2], al[2]); split1(a3, ah[3], al[3]);
        }
#pragma unroll
        for (int jj = 0; jj < 2; jj++) {
            const int n0 = nsub + 8 * jj;
            uint32_t bh[2], bl[2];
            bh[0] = __float_as_uint(sMh[(k0 + tig)     * 40 + n0 + g]);
            bh[1] = __float_as_uint(sMh[(k0 + tig + 4) * 40 + n0 + g]);
            bl[0] = __float_as_uint(sMl[(k0 + tig)     * 40 + n0 + g]);
            bl[1] = __float_as_uint(sMl[(k0 + tig + 4) * 40 + n0 + g]);
            mma8(cc2[jj], ah, bh);
            mma8(cc2[jj], ah, bl);
            mma8(cc2[jj], al, bh);
        }
    }

    // ---- write this warp's 16 rows x 16 cols ----
    const float scale = 0.125f;   // 1/sqrt(64)
    float* O = OUT + ((size_t)b * SEQ + rc * CH1) * DIM;
#pragma unroll
    for (int jj = 0; jj < 2; jj++) {
        const int colg = 32 * chf + nsub + 8 * jj + 2 * tig;
        *(float2*)&O[(size_t)(m0s + g)     * DIM + colg] =
            make_float2(cc2[jj][0] * scale, cc2[jj][1] * scale);
        *(float2*)&O[(size_t)(m0s + g + 8) * DIM + colg] =
            make_float2(cc2[jj][2] * scale, cc2[jj][3] * scale);
    }
}

// ---------------------------------------------------------------------------
extern "C" void kernel_launch(void* const* d_in, const int* in_sizes, int n_in,
                              void* d_out, int out_size)
{
    const float* q  = (const float*)d_in[0];
    const float* k  = (const float*)d_in[1];
    const float* v  = (const float*)d_in[2];
    const float* fq = (const float*)d_in[3];
    const float* fk = (const float*)d_in[4];
    const float* fv = (const float*)d_in[5];
    float* out = (float*)d_out;

    kv_outer_kernel<<<dim3(NC1, BATCH), 128>>>(k, v, fk, fv);
    reduce_a_kernel<<<256, 256>>>();
    reduce_b_kernel<<<32, 256>>>();
    qm_kernel<<<dim3(256, BATCH), 128>>>(q, fq, out);
}